// round 13
// baseline (speedup 1.0000x reference)
#include <cuda_runtime.h>
#include <cuda_bf16.h>

// GaussianSplatting2D: preprocess (Cholesky + packed tile bbox) + fused
// bin/composite render, PDL. 512 tiles of 16x8, SINGLE WAVE (4 blocks/SM,
// 32-reg cap via launch_bounds). Block = 8 partitions x 64 threads x 2 px.
// alpha = opac * ex2(-(u^2+v^2)), u = P*px + R*py + U0, v = S*py + V0.
// Exact split-transmittance combine (8-term Horner).

#define IMG_W 256
#define IMG_H 256
#define TILE_W 16
#define TILE_H 8
#define TILES_X (IMG_W / TILE_W)       // 16
#define TILES_Y (IMG_H / TILE_H)       // 32
#define NUM_TILES 512
#define PIX (TILE_W * TILE_H)          // 128
#define NPART 8
#define THREADS 512                    // 8 parts x 64 threads x 2 px
#define MAX_N 1024
#define Q_CUT 12.0f                    // measured rel_err ~1.4e-4 (tol 1e-3)
#define LOG2E 1.4426950408889634f

__device__ float4   g_p0[MAX_N];   // (P, R, U0, S)
__device__ float4   g_p1[MAX_N];   // (V0, opac, opac*color, 0)
__device__ unsigned g_tbb[MAX_N];  // packed tile bbox: xmin|xmax<<8|ymin<<16|ymax<<24

__global__ void preprocess_kernel(const float2* __restrict__ means,
                                  const float*  __restrict__ quats,
                                  const float2* __restrict__ scales,
                                  const float*  __restrict__ rgbs,
                                  const float*  __restrict__ opacities,
                                  int n) {
    int i = blockIdx.x * blockDim.x + threadIdx.x;
    if (i < n) {
        float2 mn = means[i];
        float2 sc = scales[i];
        float c, s;
        __sincosf(quats[i], &s, &c);
        float sx2 = sc.x * sc.x, sy2 = sc.y * sc.y;
        float a11 = c * c * sx2 + s * s * sy2;
        float a12 = c * s * (sx2 - sy2);
        float a22 = s * s * sx2 + c * c * sy2;
        float inv_det = 1.0f / (a11 * a22 - a12 * a12);
        float ia =  a22 * inv_det;
        float ib = -a12 * inv_det;
        float ic =  a11 * inv_det;

        float L11 = sqrtf(ia);
        float L12 = ib / L11;
        float L22 = sqrtf(ic - L12 * L12);
        float k = sqrtf(0.5f * LOG2E);
        float P = k * L11;
        float R = k * L12;
        float S = k * L22;
        float U0 = -(P * mn.x + R * mn.y);
        float V0 = -S * mn.y;

        float opac  = 1.0f / (1.0f + __expf(-opacities[i]));
        float color = 1.0f / (1.0f + __expf(-rgbs[i]));

        g_p0[i] = make_float4(P, R, U0, S);
        g_p1[i] = make_float4(V0, opac, opac * color, 0.0f);

        float rx = sqrtf(Q_CUT * a11);
        float ry = sqrtf(Q_CUT * a22);
        int xmin = max((int)floorf((mn.x - rx) * (1.0f / TILE_W)), 0);
        int xmax = min((int)floorf((mn.x + rx) * (1.0f / TILE_W)), TILES_X - 1);
        int ymin = max((int)floorf((mn.y - ry) * (1.0f / TILE_H)), 0);
        int ymax = min((int)floorf((mn.y + ry) * (1.0f / TILE_H)), TILES_Y - 1);
        g_tbb[i] = (unsigned)xmin | ((unsigned)xmax << 8) |
                   ((unsigned)ymin << 16) | ((unsigned)ymax << 24);
    }
    __threadfence();
    asm volatile("griddepcontrol.launch_dependents;" ::: "memory");
}

__device__ __forceinline__ bool tbb_hit(unsigned bb, unsigned txi, unsigned tyi) {
    return (txi >= (bb & 0xffu))         && (txi <= ((bb >> 8) & 0xffu)) &&
           (tyi >= ((bb >> 16) & 0xffu)) && (tyi <= (bb >> 24));
}

__global__ void __launch_bounds__(THREADS, 4) render_kernel(float* __restrict__ out, int n) {
    __shared__ float4 s0[MAX_N];
    __shared__ float4 s1[MAX_N];
    __shared__ int    sCnt[16];
    __shared__ int    sOff[16];
    __shared__ int    sTot;
    __shared__ float4 sComb[NPART][PIX / 2];   // (acc0,T0,acc1,T1) per pixel pair

    asm volatile("griddepcontrol.wait;" ::: "memory");

    int tile = blockIdx.x;
    int tid  = threadIdx.x;
    int lane = tid & 31;
    int w    = tid >> 5;                  // 16 warps
    unsigned lmask = (1u << lane) - 1u;

    unsigned txi = tile % TILES_X;
    unsigned tyi = tile / TILES_X;

    // ---- Phase A: single-pass ordered pair-compaction (n <= 2*THREADS) ----
    int i0 = tid * 2;
    int i1 = i0 + 1;
    bool h0 = false, h1 = false;
    if (i0 < n) {
        uint2 bb2 = *reinterpret_cast<const uint2*>(&g_tbb[i0]);   // 8B aligned
        h0 = tbb_hit(bb2.x, txi, tyi);
        h1 = (i1 < n) && tbb_hit(bb2.y, txi, tyi);
    }
    unsigned m0 = __ballot_sync(0xffffffffu, h0);
    unsigned m1 = __ballot_sync(0xffffffffu, h1);
    if (lane == 0) sCnt[w] = __popc(m0) + __popc(m1);
    __syncthreads();
    if (tid < 16) {
        int v = sCnt[tid];
        int x = v;
        #pragma unroll
        for (int d = 1; d < 16; d <<= 1) {
            int y = __shfl_up_sync(0x0000ffffu, x, d);
            if (tid >= d) x += y;
        }
        sOff[tid] = x - v;
        if (tid == 15) sTot = x;
    }
    __syncthreads();
    {
        int pre = sOff[w] + __popc(m0 & lmask) + __popc(m1 & lmask);
        if (h0) { s0[pre] = g_p0[i0]; s1[pre] = g_p1[i0]; pre++; }
        if (h1) { s0[pre] = g_p0[i1]; s1[pre] = g_p1[i1]; }
    }
    __syncthreads();
    int total = sTot;

    // ---- Phase B: compositing, 8-way split, 2 adjacent pixels per thread ----
    int part = tid >> 6;                 // 0..7
    int pq   = tid & 63;                 // pixel-pair index
    int pyr  = pq >> 3;                  // (pq*2)>>4: row 0..7
    int pxc  = (pq & 7) * 2;             // even column 0..14
    float px0 = (float)((int)txi * TILE_W + pxc) + 0.5f;
    float px1 = px0 + 1.0f;
    float pyf = (float)((int)tyi * TILE_H + pyr) + 0.5f;

    int len = (total + NPART - 1) >> 3;
    int jb  = min(part * len, total);
    int je  = min(jb + len, total);

    float T0 = 1.0f, acc0 = 0.0f;
    float T1 = 1.0f, acc1 = 0.0f;

    #pragma unroll 4
    for (int j = jb; j < je; j++) {
        float4 a = s0[j];
        float4 b = s1[j];
        float uy  = fmaf(a.y, pyf, a.z);     // R*py + U0   (shared)
        float v   = fmaf(a.w, pyf, b.x);     // S*py + V0   (shared)
        float nvv = -(v * v);
        float u0 = fmaf(a.x, px0, uy);
        float u1 = fmaf(a.x, px1, uy);
        float q0 = fmaf(u0, -u0, nvv);
        float q1 = fmaf(u1, -u1, nvv);
        float e0, e1;
        asm("ex2.approx.ftz.f32 %0, %1;" : "=f"(e0) : "f"(q0));
        asm("ex2.approx.ftz.f32 %0, %1;" : "=f"(e1) : "f"(q1));
        float wt0 = e0 * T0;
        float wt1 = e1 * T1;
        acc0 = fmaf(b.z, wt0, acc0);
        acc1 = fmaf(b.z, wt1, acc1);
        T0   = fmaf(-b.y, wt0, T0);
        T1   = fmaf(-b.y, wt1, T1);
    }

    sComb[part][pq] = make_float4(acc0, T0, acc1, T1);
    __syncthreads();

    // ---- Combine: 8-term Horner, front-to-back; thread handles one pair ----
    if (tid < PIX / 2) {
        float4 c7 = sComb[7][tid];
        float r0 = c7.x, r1 = c7.z;
        #pragma unroll
        for (int p = 6; p >= 0; p--) {
            float4 cp = sComb[p][tid];
            r0 = fmaf(cp.y, r0, cp.x);
            r1 = fmaf(cp.w, r1, cp.z);
        }
        int pyro = tid >> 3;
        int pxco = (tid & 7) * 2;
        int opx = (int)txi * TILE_W + pxco;
        int opy = (int)tyi * TILE_H + pyro;
        *reinterpret_cast<float2*>(&out[opy * IMG_W + opx]) = make_float2(r0, r1);
    }
}

extern "C" void kernel_launch(void* const* d_in, const int* in_sizes, int n_in,
                              void* d_out, int out_size) {
    const float2* means     = (const float2*)d_in[0];
    const float*  quats     = (const float*)d_in[1];
    const float2* scales    = (const float2*)d_in[2];
    const float*  rgbs      = (const float*)d_in[3];
    const float*  opacities = (const float*)d_in[4];
    float* out = (float*)d_out;

    int n = in_sizes[1];
    if (n > MAX_N) n = MAX_N;

    preprocess_kernel<<<4, 256>>>(means, quats, scales, rgbs, opacities, n);

    cudaLaunchConfig_t cfg = {};
    cfg.gridDim  = dim3(NUM_TILES);
    cfg.blockDim = dim3(THREADS);
    cfg.dynamicSmemBytes = 0;
    cfg.stream = 0;
    cudaLaunchAttribute attrs[1];
    attrs[0].id = cudaLaunchAttributeProgrammaticStreamSerialization;
    attrs[0].val.programmaticStreamSerializationAllowed = 1;
    cfg.attrs = attrs;
    cfg.numAttrs = 1;
    cudaError_t e = cudaLaunchKernelEx(&cfg, render_kernel, out, n);
    if (e != cudaSuccess) {
        render_kernel<<<NUM_TILES, THREADS>>>(out, n);
    }
}

// round 14
// speedup vs baseline: 1.2330x; 1.2330x over previous
#include <cuda_runtime.h>
#include <cuda_bf16.h>

// GaussianSplatting2D: SINGLE kernel. Cheap conservative cull (no sincos:
// r = sqrt(Q)*max(sx,sy) >= exact bbox radius), ordered index compaction,
// DENSE per-hit param computation (only `total` threads pay sincos/Cholesky),
// then 8-way split-transmittance compositing, 2 adjacent px per thread.
// alpha = opac * ex2(-(u^2+v^2)), u = P*px + R*py + U0, v = S*py + V0.

#define IMG_W 256
#define IMG_H 256
#define TILE_W 16
#define TILE_H 8
#define TILES_X (IMG_W / TILE_W)       // 16
#define NUM_TILES 512
#define PIX (TILE_W * TILE_H)          // 128
#define NPART 8
#define THREADS 512                    // 8 parts x 64 threads x 2 px
#define MAX_N 1024
#define Q_CUT 12.0f                    // measured rel_err ~1.4e-4 (tol 1e-3)
#define SQRT_Q 3.4641016f              // sqrt(12)
#define LOG2E 1.4426950408889634f

__global__ void __launch_bounds__(THREADS, 4) splat_kernel(
    const float*  __restrict__ means,     // (N,2)
    const float*  __restrict__ quats,
    const float*  __restrict__ scales,    // (N,2)
    const float*  __restrict__ rgbs,
    const float*  __restrict__ opacities,
    float* __restrict__ out,
    int n)
{
    __shared__ float4 s0[MAX_N];   // (P, R, U0, S)
    __shared__ float4 s1[MAX_N];   // (V0, opac, opac*color, 0)
    __shared__ int    sIdx[MAX_N];
    __shared__ int    sCnt[16];
    __shared__ int    sOff[16];
    __shared__ int    sTot;
    __shared__ float4 sComb[NPART][PIX / 2];   // (acc0,T0,acc1,T1) per px pair

    int tile = blockIdx.x;
    int tid  = threadIdx.x;
    int lane = tid & 31;
    int w    = tid >> 5;                  // 16 warps
    unsigned lmask = (1u << lane) - 1u;

    int txi = tile % TILES_X;
    int tyi = tile / TILES_X;
    float tcx = (float)(txi * TILE_W) + 0.5f * TILE_W;   // tile center
    float tcy = (float)(tyi * TILE_H) + 0.5f * TILE_H;

    // ---- Phase A1: cheap conservative cull, candidates 2t, 2t+1 ----
    int i0 = tid * 2;
    int i1 = i0 + 1;
    bool h0 = false, h1 = false;
    if (i1 < n) {
        float4 mn2 = *reinterpret_cast<const float4*>(&means[i0 * 2]);   // both means
        float4 sc2 = *reinterpret_cast<const float4*>(&scales[i0 * 2]);  // both scales
        float r0 = SQRT_Q * fmaxf(sc2.x, sc2.y);
        float r1 = SQRT_Q * fmaxf(sc2.z, sc2.w);
        h0 = (fabsf(mn2.x - tcx) <= r0 + 0.5f * TILE_W) &&
             (fabsf(mn2.y - tcy) <= r0 + 0.5f * TILE_H);
        h1 = (fabsf(mn2.z - tcx) <= r1 + 0.5f * TILE_W) &&
             (fabsf(mn2.w - tcy) <= r1 + 0.5f * TILE_H);
    } else if (i0 < n) {
        float mx = means[i0 * 2], my = means[i0 * 2 + 1];
        float r0 = SQRT_Q * fmaxf(scales[i0 * 2], scales[i0 * 2 + 1]);
        h0 = (fabsf(mx - tcx) <= r0 + 0.5f * TILE_W) &&
             (fabsf(my - tcy) <= r0 + 0.5f * TILE_H);
    }
    unsigned m0 = __ballot_sync(0xffffffffu, h0);
    unsigned m1 = __ballot_sync(0xffffffffu, h1);
    if (lane == 0) sCnt[w] = __popc(m0) + __popc(m1);
    __syncthreads();
    if (tid < 16) {
        int v = sCnt[tid];
        int x = v;
        #pragma unroll
        for (int d = 1; d < 16; d <<= 1) {
            int y = __shfl_up_sync(0x0000ffffu, x, d);
            if (tid >= d) x += y;
        }
        sOff[tid] = x - v;
        if (tid == 15) sTot = x;
    }
    __syncthreads();
    {
        int pre = sOff[w] + __popc(m0 & lmask) + __popc(m1 & lmask);
        if (h0) sIdx[pre++] = i0;
        if (h1) sIdx[pre] = i1;
    }
    __syncthreads();
    int total = sTot;

    // ---- Phase A2: dense param computation, one hit per thread ----
    for (int j = tid; j < total; j += THREADS) {
        int i = sIdx[j];
        float mx = means[i * 2], my = means[i * 2 + 1];
        float sx = scales[i * 2], sy = scales[i * 2 + 1];
        float c, s;
        __sincosf(quats[i], &s, &c);
        float sx2 = sx * sx, sy2 = sy * sy;
        float a11 = c * c * sx2 + s * s * sy2;
        float a12 = c * s * (sx2 - sy2);
        float a22 = s * s * sx2 + c * c * sy2;
        float inv_det = 1.0f / (a11 * a22 - a12 * a12);
        float ia =  a22 * inv_det;
        float ib = -a12 * inv_det;
        float ic =  a11 * inv_det;
        float L11 = sqrtf(ia);
        float L12 = ib / L11;
        float L22 = sqrtf(ic - L12 * L12);
        float kk = sqrtf(0.5f * LOG2E);
        float P = kk * L11;
        float R = kk * L12;
        float S = kk * L22;
        float U0 = -(P * mx + R * my);
        float V0 = -S * my;
        float opac  = 1.0f / (1.0f + __expf(-opacities[i]));
        float color = 1.0f / (1.0f + __expf(-rgbs[i]));
        s0[j] = make_float4(P, R, U0, S);
        s1[j] = make_float4(V0, opac, opac * color, 0.0f);
    }
    __syncthreads();

    // ---- Phase B: compositing, 8-way split, 2 adjacent pixels per thread ----
    int part = tid >> 6;                 // 0..7
    int pq   = tid & 63;                 // pixel-pair index
    int pyr  = pq >> 3;                  // row 0..7
    int pxc  = (pq & 7) * 2;             // even column
    float px0 = (float)(txi * TILE_W + pxc) + 0.5f;
    float px1 = px0 + 1.0f;
    float pyf = (float)(tyi * TILE_H + pyr) + 0.5f;

    int len = (total + NPART - 1) >> 3;
    int jb  = min(part * len, total);
    int je  = min(jb + len, total);

    float T0 = 1.0f, acc0 = 0.0f;
    float T1 = 1.0f, acc1 = 0.0f;

    #pragma unroll 4
    for (int j = jb; j < je; j++) {
        float4 a = s0[j];
        float4 b = s1[j];
        float uy  = fmaf(a.y, pyf, a.z);     // R*py + U0   (shared)
        float v   = fmaf(a.w, pyf, b.x);     // S*py + V0   (shared)
        float nvv = -(v * v);
        float u0 = fmaf(a.x, px0, uy);
        float u1 = fmaf(a.x, px1, uy);
        float q0 = fmaf(u0, -u0, nvv);
        float q1 = fmaf(u1, -u1, nvv);
        float e0, e1;
        asm("ex2.approx.ftz.f32 %0, %1;" : "=f"(e0) : "f"(q0));
        asm("ex2.approx.ftz.f32 %0, %1;" : "=f"(e1) : "f"(q1));
        float wt0 = e0 * T0;
        float wt1 = e1 * T1;
        acc0 = fmaf(b.z, wt0, acc0);
        acc1 = fmaf(b.z, wt1, acc1);
        T0   = fmaf(-b.y, wt0, T0);
        T1   = fmaf(-b.y, wt1, T1);
    }

    sComb[part][pq] = make_float4(acc0, T0, acc1, T1);
    __syncthreads();

    // ---- Combine: 8-term Horner, front-to-back; one pixel pair per thread ----
    if (tid < PIX / 2) {
        float4 c7 = sComb[7][tid];
        float r0 = c7.x, r1 = c7.z;
        #pragma unroll
        for (int p = 6; p >= 0; p--) {
            float4 cp = sComb[p][tid];
            r0 = fmaf(cp.y, r0, cp.x);
            r1 = fmaf(cp.w, r1, cp.z);
        }
        int pyro = tid >> 3;
        int pxco = (tid & 7) * 2;
        int opx = txi * TILE_W + pxco;
        int opy = tyi * TILE_H + pyro;
        *reinterpret_cast<float2*>(&out[opy * IMG_W + opx]) = make_float2(r0, r1);
    }
}

extern "C" void kernel_launch(void* const* d_in, const int* in_sizes, int n_in,
                              void* d_out, int out_size) {
    const float* means     = (const float*)d_in[0];
    const float* quats     = (const float*)d_in[1];
    const float* scales    = (const float*)d_in[2];
    const float* rgbs      = (const float*)d_in[3];
    const float* opacities = (const float*)d_in[4];
    float* out = (float*)d_out;

    int n = in_sizes[1];
    if (n > MAX_N) n = MAX_N;

    splat_kernel<<<NUM_TILES, THREADS>>>(means, quats, scales, rgbs, opacities, out, n);
}